// round 3
// baseline (speedup 1.0000x reference)
#include <cuda_runtime.h>
#include <cuda_bf16.h>

// GANLoss: out = -mean(prob[n, targets[n]] * reward[n]), N=8192, C=32000.
// Latency-bound gather. Single fused kernel: per-block partials + threadfence
// last-block-done reduction (int atomic counter only -> deterministic).
// Counter is reset by the last block so graph replays are reentrant.

#define NBLOCKS 32
#define NTHREADS 256

__device__ float g_partials[NBLOCKS];
__device__ int   g_count = 0;

__global__ __launch_bounds__(NTHREADS) void ganloss_kernel(
    const float* __restrict__ prob,
    const int* __restrict__ targets,
    const float* __restrict__ reward,
    float* __restrict__ out,
    int N, long long C, float inv_n)
{
    int idx = blockIdx.x * blockDim.x + threadIdx.x;

    float v = 0.0f;
    if (idx < N) {
        int t = targets[idx];
        v = __ldg(&prob[(long long)idx * C + (long long)t]) * __ldg(&reward[idx]);
    }

    // intra-block reduce
    #pragma unroll
    for (int off = 16; off > 0; off >>= 1)
        v += __shfl_xor_sync(0xFFFFFFFFu, v, off);

    __shared__ float s_warp[NTHREADS / 32];
    __shared__ bool  s_last;
    int lane = threadIdx.x & 31;
    int wid  = threadIdx.x >> 5;
    if (lane == 0) s_warp[wid] = v;
    __syncthreads();

    if (threadIdx.x < 32) {
        float w = (lane < NTHREADS / 32) ? s_warp[lane] : 0.0f;
        #pragma unroll
        for (int off = 4; off > 0; off >>= 1)
            w += __shfl_xor_sync(0xFFFFFFFFu, w, off);
        if (lane == 0) {
            g_partials[blockIdx.x] = w;
            __threadfence();
            int old = atomicAdd(&g_count, 1);
            s_last = (old == NBLOCKS - 1);
        }
    }
    __syncthreads();

    // last arriving block: reduce the 32 partials (fixed order), write result
    if (s_last && threadIdx.x < 32) {
        __threadfence();  // make all partials visible
        float p = g_partials[threadIdx.x];
        #pragma unroll
        for (int off = 16; off > 0; off >>= 1)
            p += __shfl_xor_sync(0xFFFFFFFFu, p, off);
        if (threadIdx.x == 0) {
            out[0] = -p * inv_n;
            __threadfence();
            g_count = 0;   // reset for next graph replay
        }
    }
}

extern "C" void kernel_launch(void* const* d_in, const int* in_sizes, int n_in,
                              void* d_out, int out_size)
{
    const float* prob    = (const float*)d_in[0];
    const int*   targets = (const int*)d_in[1];
    const float* reward  = (const float*)d_in[2];
    float*       out     = (float*)d_out;

    const int N = in_sizes[2];                       // 8192
    const long long C = (long long)in_sizes[0] / N;  // 32000

    ganloss_kernel<<<NBLOCKS, NTHREADS>>>(prob, targets, reward, out,
                                          N, C, 1.0f / (float)N);
}

// round 4
// speedup vs baseline: 1.1878x; 1.1878x over previous
#include <cuda_runtime.h>
#include <cuda_bf16.h>

// GANLoss: out = -mean(prob[n, targets[n]] * reward[n]), N=8192, C=32000.
// Latency-bound gather. One memset node zeroes out[0]; the gather kernel
// warp-reduces and fires one no-return float atomicAdd (REDG) per warp,
// pre-scaled by -1/N. No inter-block sync, no fences, no second kernel.

#define NBLOCKS  64
#define NTHREADS 128

__global__ __launch_bounds__(NTHREADS) void ganloss_kernel(
    const float* __restrict__ prob,
    const int* __restrict__ targets,
    const float* __restrict__ reward,
    float* __restrict__ out,
    int N, long long C, float neg_inv_n)
{
    int idx = blockIdx.x * blockDim.x + threadIdx.x;

    float v = 0.0f;
    if (idx < N) {
        int t = targets[idx];
        v = __ldg(&prob[(long long)idx * C + (long long)t]) * __ldg(&reward[idx]);
    }

    // warp reduce (5 shuffles)
    #pragma unroll
    for (int off = 16; off > 0; off >>= 1)
        v += __shfl_xor_sync(0xFFFFFFFFu, v, off);

    // one REDG per warp, pre-scaled; no return value -> no-return reduction
    if ((threadIdx.x & 31) == 0)
        atomicAdd(out, v * neg_inv_n);
}

extern "C" void kernel_launch(void* const* d_in, const int* in_sizes, int n_in,
                              void* d_out, int out_size)
{
    const float* prob    = (const float*)d_in[0];
    const int*   targets = (const int*)d_in[1];
    const float* reward  = (const float*)d_in[2];
    float*       out     = (float*)d_out;

    const int N = in_sizes[2];                       // 8192
    const long long C = (long long)in_sizes[0] / N;  // 32000

    cudaMemsetAsync(out, 0, sizeof(float));
    ganloss_kernel<<<NBLOCKS, NTHREADS>>>(prob, targets, reward, out,
                                          N, C, -1.0f / (float)N);
}